// round 10
// baseline (speedup 1.0000x reference)
#include <cuda_runtime.h>
#include <cuda_fp16.h>
#include <cstdint>

#define NDIM 128
#define MAX_NODES 100000

// Scratch: fp16 z table, fp16 x_source copy, dtype flag.
__device__ __half g_z_h[MAX_NODES * NDIM];    // 25.6 MB
__device__ __half g_xs_h[MAX_NODES * NDIM];   // 25.6 MB
__device__ int    g_idx_is64;

// ---------------------------------------------------------------------------
// Kernel 0: detect index dtype (int64 values < 2^31 -> all odd words zero).
// ---------------------------------------------------------------------------
__global__ void detect_idx_kernel(const int* __restrict__ idx_words, int nwords) {
    __shared__ int s_any_nonzero;
    if (threadIdx.x == 0) s_any_nonzero = 0;
    __syncthreads();
    for (int i = 1 + 2 * threadIdx.x; i < nwords; i += 2 * blockDim.x) {
        if (idx_words[i] != 0) { s_any_nonzero = 1; break; }
    }
    __syncthreads();
    if (threadIdx.x == 0) g_idx_is64 = (s_any_nonzero == 0) ? 1 : 0;
}

// ---------------------------------------------------------------------------
// Kernel 1: convert x_source -> fp16 (vectorized x4)
// ---------------------------------------------------------------------------
__global__ void __launch_bounds__(256) convert_xs_kernel(const float* __restrict__ xs,
                                                         int n_elem4) {
    int i = blockIdx.x * blockDim.x + threadIdx.x;
    if (i >= n_elem4) return;
    float4 v = *(const float4*)(xs + (size_t)i * 4);
    *(__half2*)(g_xs_h + (size_t)i * 4)     = __floats2half2_rn(v.x, v.y);
    *(__half2*)(g_xs_h + (size_t)i * 4 + 2) = __floats2half2_rn(v.z, v.w);
}

// ---------------------------------------------------------------------------
// Kernel 2: tensor-core GEMM  z[m][d] = sum_f xt[m][f] * W[d][f]
// mma.sync.m16n8k16.row.col.f32.f16.f16.f32, MINIMAL register state:
//   - n-tile OUTER loop (unroll 1), K inner (unroll 1)
//   - exactly 4 scalar fp32 accumulators, no register arrays
//   - A fragments: float2 from fp32 xt + in-register cvt (L1-hot re-reads)
//   - B fragments: W staged once into shared fp16; W row-major IS the
//     .col B layout (B[k][n] = W[n][k]); 272B row stride -> conflict-free.
// Block: 256 thr = 8 warps x 16 rows = 128 rows/block.
// ---------------------------------------------------------------------------
__global__ void __launch_bounds__(256) gemm_mma_kernel(const float* __restrict__ xt,
                                                       const float* __restrict__ W,
                                                       int n_rows) {
    __shared__ __half W_sh[NDIM][NDIM + 8];

    for (int i = threadIdx.x; i < NDIM * NDIM; i += 256) {
        int r = i >> 7;
        int c = i & (NDIM - 1);
        W_sh[r][c] = __float2half_rn(W[i]);
    }
    __syncthreads();

    const int warp = threadIdx.x >> 5;
    const int lane = threadIdx.x & 31;
    const int g = lane >> 2;        // 0..7
    const int t = lane & 3;         // 0..3
    const int row_base = blockIdx.x * 128 + warp * 16;
    if (row_base >= n_rows) return;

    // clamp fragment rows so tail blocks never read OOB (stores are guarded)
    int r0 = row_base + g;      if (r0 >= n_rows) r0 = n_rows - 1;
    int r1 = row_base + g + 8;  if (r1 >= n_rows) r1 = n_rows - 1;
    const float* A0 = xt + (size_t)r0 * NDIM + 2 * t;
    const float* A1 = xt + (size_t)r1 * NDIM + 2 * t;

    const int row0 = row_base + g;
    const int row1 = row_base + g + 8;

#pragma unroll 1
    for (int nt = 0; nt < 16; nt++) {
        const int n0 = nt * 8;
        float c0 = 0.f, c1 = 0.f, c2 = 0.f, c3 = 0.f;

#pragma unroll 1
        for (int k0 = 0; k0 < NDIM; k0 += 16) {
            float2 f0 = *(const float2*)(A0 + k0);
            float2 f1 = *(const float2*)(A1 + k0);
            float2 f2 = *(const float2*)(A0 + k0 + 8);
            float2 f3 = *(const float2*)(A1 + k0 + 8);
            __half2 h0 = __floats2half2_rn(f0.x, f0.y);
            __half2 h1 = __floats2half2_rn(f1.x, f1.y);
            __half2 h2 = __floats2half2_rn(f2.x, f2.y);
            __half2 h3 = __floats2half2_rn(f3.x, f3.y);
            unsigned int a0 = *(unsigned int*)&h0;
            unsigned int a1 = *(unsigned int*)&h1;
            unsigned int a2 = *(unsigned int*)&h2;
            unsigned int a3 = *(unsigned int*)&h3;
            unsigned int b0 = *(const unsigned int*)&W_sh[n0 + g][k0 + 2 * t];
            unsigned int b1 = *(const unsigned int*)&W_sh[n0 + g][k0 + 2 * t + 8];
            asm volatile(
                "mma.sync.aligned.m16n8k16.row.col.f32.f16.f16.f32 "
                "{%0,%1,%2,%3}, {%4,%5,%6,%7}, {%8,%9}, {%0,%1,%2,%3};"
                : "+f"(c0), "+f"(c1), "+f"(c2), "+f"(c3)
                : "r"(a0), "r"(a1), "r"(a2), "r"(a3), "r"(b0), "r"(b1));
        }

        const int col = n0 + 2 * t;
        if (row0 < n_rows)
            *(__half2*)(g_z_h + (size_t)row0 * NDIM + col) = __floats2half2_rn(c0, c1);
        if (row1 < n_rows)
            *(__half2*)(g_z_h + (size_t)row1 * NDIM + col) = __floats2half2_rn(c2, c3);
    }
}

// ---------------------------------------------------------------------------
// Kernel 3: per-edge dot on fp16 tables (unchanged from the 225.6us pass).
// 16 lanes per edge, 8 edges per warp (4 unrolled pairs), all loads hoisted.
// ---------------------------------------------------------------------------
__device__ __forceinline__ float dot8h(float4 a, float4 v) {
    const __half2* ah = (const __half2*)&a;
    const __half2* vh = (const __half2*)&v;
    float acc = 0.f;
#pragma unroll
    for (int i = 0; i < 4; i++) {
        float2 af = __half22float2(ah[i]);
        float2 vf = __half22float2(vh[i]);
        acc += af.x * vf.x + af.y * vf.y;
    }
    return acc;
}

#define EDGES_PER_WARP 8

__global__ void __launch_bounds__(256) edge_dot_kernel(
    const void* __restrict__ eli_raw,
    const float* __restrict__ bias,
    float* __restrict__ out,
    int E, int N) {
    const int gwarp = (blockIdx.x * blockDim.x + threadIdx.x) >> 5;
    const int lane  = threadIdx.x & 31;
    const int half  = lane >> 4;
    const int sub   = lane & 15;

    const int e0 = gwarp * EDGES_PER_WARP;
    if (e0 >= E) return;

    const int is64 = g_idx_is64;
    const long long* eli64 = (const long long*)eli_raw;
    const int*       eli32 = (const int*)eli_raw;

    int eidx[4];
    long long sIdx[4], tIdx[4];
#pragma unroll
    for (int j = 0; j < 4; j++) {
        int e = e0 + 2 * j + half;
        if (e >= E) e = E - 1;
        eidx[j] = e;
        long long s, t;
        if (is64) { s = __ldg(&eli64[e]); t = __ldg(&eli64[(long long)E + e]); }
        else      { s = __ldg(&eli32[e]); t = __ldg(&eli32[(long long)E + e]); }
        if (s < 0) s = 0; if (s >= N) s = N - 1;
        if (t < 0) t = 0; if (t >= N) t = N - 1;
        sIdx[j] = s; tIdx[j] = t;
    }

    float4 a[4], v[4];
#pragma unroll
    for (int j = 0; j < 4; j++) {
        a[j] = __ldg((const float4*)(g_xs_h + ((size_t)sIdx[j] << 7) + (sub << 3)));
        v[j] = __ldg((const float4*)(g_z_h  + ((size_t)tIdx[j] << 7) + (sub << 3)));
    }

    const float bv = __ldg(bias);

#pragma unroll
    for (int j = 0; j < 4; j++) {
        float acc = dot8h(a[j], v[j]);
#pragma unroll
        for (int o = 8; o > 0; o >>= 1)
            acc += __shfl_down_sync(0xFFFFFFFFu, acc, o, 16);
        if (sub == 0 && (e0 + 2 * j + half) < E)
            out[eidx[j]] = acc + bv;
    }
}

// ---------------------------------------------------------------------------
extern "C" void kernel_launch(void* const* d_in, const int* in_sizes, int n_in,
                              void* d_out, int out_size) {
    const float* x_source = nullptr;
    const float* x_target = nullptr;
    const void*  eli      = nullptr;
    const float* W        = nullptr;
    const float* bias     = nullptr;
    int N = 0;
    const int E = out_size;

    for (int i = 0; i < n_in; i++) {
        int sz = in_sizes[i];
        if (sz == NDIM * NDIM)      W    = (const float*)d_in[i];
        else if (sz == 1)           bias = (const float*)d_in[i];
        else if (sz == 2 * E)       eli  = d_in[i];
        else {
            if (!x_source) { x_source = (const float*)d_in[i]; N = sz / NDIM; }
            else           { x_target = (const float*)d_in[i]; }
        }
    }

    float* out = (float*)d_out;

    // 0) detect index dtype
    int nwords = 2 * E; if (nwords > 4096) nwords = 4096;
    detect_idx_kernel<<<1, 256>>>((const int*)eli, nwords);

    // 1) convert x_source -> fp16
    int n_elem4 = (N * NDIM) / 4;
    convert_xs_kernel<<<(n_elem4 + 255) / 256, 256>>>(x_source, n_elem4);

    // 2) z = x_target @ W^T via tensor cores (128 rows per block)
    gemm_mma_kernel<<<(N + 127) / 128, 256>>>(x_target, W, N);

    // 3) per-edge gather + dot
    int warps_needed = (E + EDGES_PER_WARP - 1) / EDGES_PER_WARP;
    int nblocks = (warps_needed + 7) / 8;
    edge_dot_kernel<<<nblocks, 256>>>(eli, bias, out, E, N);
}

// round 11
// speedup vs baseline: 1.4667x; 1.4667x over previous
#include <cuda_runtime.h>
#include <cuda_fp16.h>
#include <cstdint>

#define NDIM 128
#define MAX_NODES 100000

// Scratch: fp16 z table, fp16 x_source copy, dtype flag.
__device__ __half g_z_h[MAX_NODES * NDIM];    // 25.6 MB
__device__ __half g_xs_h[MAX_NODES * NDIM];   // 25.6 MB
__device__ int    g_idx_is64;

// ---------------------------------------------------------------------------
// Kernel 0: detect index dtype (int64 values < 2^31 -> all odd words zero).
// ---------------------------------------------------------------------------
__global__ void detect_idx_kernel(const int* __restrict__ idx_words, int nwords) {
    __shared__ int s_any_nonzero;
    if (threadIdx.x == 0) s_any_nonzero = 0;
    __syncthreads();
    for (int i = 1 + 2 * threadIdx.x; i < nwords; i += 2 * blockDim.x) {
        if (idx_words[i] != 0) { s_any_nonzero = 1; break; }
    }
    __syncthreads();
    if (threadIdx.x == 0) g_idx_is64 = (s_any_nonzero == 0) ? 1 : 0;
}

// ---------------------------------------------------------------------------
// Kernel 1: convert x_source -> fp16 (vectorized x4)
// ---------------------------------------------------------------------------
__global__ void __launch_bounds__(256) convert_xs_kernel(const float* __restrict__ xs,
                                                         int n_elem4) {
    int i = blockIdx.x * blockDim.x + threadIdx.x;
    if (i >= n_elem4) return;
    float4 v = *(const float4*)(xs + (size_t)i * 4);
    *(__half2*)(g_xs_h + (size_t)i * 4)     = __floats2half2_rn(v.x, v.y);
    *(__half2*)(g_xs_h + (size_t)i * 4 + 2) = __floats2half2_rn(v.z, v.w);
}

// ---------------------------------------------------------------------------
// Kernel 2: tensor-core GEMM  z[m][d] = sum_f xt[m][f] * W[d][f]
// mma.sync.m16n8k16.row.col.f32.f16.f16.f32
// R10's clean skeleton + 4x n-subtiling with 16 NAMED SCALAR accumulators
// (register arrays here get demoted to local memory -> 128 MiB pool growth
//  -> harness violation; scalars proven safe in R10).
// Per K-step: load A fragment ONCE, issue 4 HMMA against 4 B subtiles.
// Block: 256 thr = 8 warps x 16 rows = 128 rows/block.
// ---------------------------------------------------------------------------
__global__ void __launch_bounds__(256) gemm_mma_kernel(const float* __restrict__ xt,
                                                       const float* __restrict__ W,
                                                       int n_rows) {
    __shared__ __half W_sh[NDIM][NDIM + 8];

    for (int i = threadIdx.x; i < NDIM * NDIM; i += 256) {
        int r = i >> 7;
        int c = i & (NDIM - 1);
        W_sh[r][c] = __float2half_rn(W[i]);
    }
    __syncthreads();

    const int warp = threadIdx.x >> 5;
    const int lane = threadIdx.x & 31;
    const int g = lane >> 2;        // 0..7
    const int t = lane & 3;         // 0..3
    const int row_base = blockIdx.x * 128 + warp * 16;
    if (row_base >= n_rows) return;

    // clamp fragment rows so tail blocks never read OOB (stores are guarded)
    int r0 = row_base + g;      if (r0 >= n_rows) r0 = n_rows - 1;
    int r1 = row_base + g + 8;  if (r1 >= n_rows) r1 = n_rows - 1;
    const float* A0 = xt + (size_t)r0 * NDIM + 2 * t;
    const float* A1 = xt + (size_t)r1 * NDIM + 2 * t;

    const int row0 = row_base + g;
    const int row1 = row_base + g + 8;

#define MMA_STEP(C0, C1, C2, C3, NROW)                                         \
    {                                                                          \
        unsigned int b0 = *(const unsigned int*)&W_sh[(NROW) + g][k0 + 2 * t]; \
        unsigned int b1 = *(const unsigned int*)&W_sh[(NROW) + g][k0 + 2 * t + 8]; \
        asm volatile(                                                          \
            "mma.sync.aligned.m16n8k16.row.col.f32.f16.f16.f32 "               \
            "{%0,%1,%2,%3}, {%4,%5,%6,%7}, {%8,%9}, {%0,%1,%2,%3};"            \
            : "+f"(C0), "+f"(C1), "+f"(C2), "+f"(C3)                           \
            : "r"(a0), "r"(a1), "r"(a2), "r"(a3), "r"(b0), "r"(b1));           \
    }

#pragma unroll 1
    for (int ntg = 0; ntg < 4; ntg++) {
        const int n0 = ntg * 32;
        float c00 = 0.f, c01 = 0.f, c02 = 0.f, c03 = 0.f;
        float c10 = 0.f, c11 = 0.f, c12 = 0.f, c13 = 0.f;
        float c20 = 0.f, c21 = 0.f, c22 = 0.f, c23 = 0.f;
        float c30 = 0.f, c31 = 0.f, c32 = 0.f, c33 = 0.f;

#pragma unroll 1
        for (int k0 = 0; k0 < NDIM; k0 += 16) {
            // A fragment loaded ONCE per k-step (shared by 4 subtile MMAs)
            float2 f0 = *(const float2*)(A0 + k0);
            float2 f1 = *(const float2*)(A1 + k0);
            float2 f2 = *(const float2*)(A0 + k0 + 8);
            float2 f3 = *(const float2*)(A1 + k0 + 8);
            __half2 h0 = __floats2half2_rn(f0.x, f0.y);
            __half2 h1 = __floats2half2_rn(f1.x, f1.y);
            __half2 h2 = __floats2half2_rn(f2.x, f2.y);
            __half2 h3 = __floats2half2_rn(f3.x, f3.y);
            unsigned int a0 = *(unsigned int*)&h0;
            unsigned int a1 = *(unsigned int*)&h1;
            unsigned int a2 = *(unsigned int*)&h2;
            unsigned int a3 = *(unsigned int*)&h3;

            MMA_STEP(c00, c01, c02, c03, n0)
            MMA_STEP(c10, c11, c12, c13, n0 + 8)
            MMA_STEP(c20, c21, c22, c23, n0 + 16)
            MMA_STEP(c30, c31, c32, c33, n0 + 24)
        }

        const int colb = n0 + 2 * t;
        if (row0 < n_rows) {
            __half* zp = g_z_h + (size_t)row0 * NDIM;
            *(__half2*)(zp + colb)      = __floats2half2_rn(c00, c01);
            *(__half2*)(zp + colb + 8)  = __floats2half2_rn(c10, c11);
            *(__half2*)(zp + colb + 16) = __floats2half2_rn(c20, c21);
            *(__half2*)(zp + colb + 24) = __floats2half2_rn(c30, c31);
        }
        if (row1 < n_rows) {
            __half* zp = g_z_h + (size_t)row1 * NDIM;
            *(__half2*)(zp + colb)      = __floats2half2_rn(c02, c03);
            *(__half2*)(zp + colb + 8)  = __floats2half2_rn(c12, c13);
            *(__half2*)(zp + colb + 16) = __floats2half2_rn(c22, c23);
            *(__half2*)(zp + colb + 24) = __floats2half2_rn(c32, c33);
        }
    }
#undef MMA_STEP
}

// ---------------------------------------------------------------------------
// Kernel 3: per-edge dot on fp16 tables (unchanged from the 225.6us pass).
// 16 lanes per edge, 8 edges per warp (4 unrolled pairs), all loads hoisted.
// ---------------------------------------------------------------------------
__device__ __forceinline__ float dot8h(float4 a, float4 v) {
    const __half2* ah = (const __half2*)&a;
    const __half2* vh = (const __half2*)&v;
    float acc = 0.f;
#pragma unroll
    for (int i = 0; i < 4; i++) {
        float2 af = __half22float2(ah[i]);
        float2 vf = __half22float2(vh[i]);
        acc += af.x * vf.x + af.y * vf.y;
    }
    return acc;
}

#define EDGES_PER_WARP 8

__global__ void __launch_bounds__(256) edge_dot_kernel(
    const void* __restrict__ eli_raw,
    const float* __restrict__ bias,
    float* __restrict__ out,
    int E, int N) {
    const int gwarp = (blockIdx.x * blockDim.x + threadIdx.x) >> 5;
    const int lane  = threadIdx.x & 31;
    const int half  = lane >> 4;
    const int sub   = lane & 15;

    const int e0 = gwarp * EDGES_PER_WARP;
    if (e0 >= E) return;

    const int is64 = g_idx_is64;
    const long long* eli64 = (const long long*)eli_raw;
    const int*       eli32 = (const int*)eli_raw;

    int eidx[4];
    long long sIdx[4], tIdx[4];
#pragma unroll
    for (int j = 0; j < 4; j++) {
        int e = e0 + 2 * j + half;
        if (e >= E) e = E - 1;
        eidx[j] = e;
        long long s, t;
        if (is64) { s = __ldg(&eli64[e]); t = __ldg(&eli64[(long long)E + e]); }
        else      { s = __ldg(&eli32[e]); t = __ldg(&eli32[(long long)E + e]); }
        if (s < 0) s = 0; if (s >= N) s = N - 1;
        if (t < 0) t = 0; if (t >= N) t = N - 1;
        sIdx[j] = s; tIdx[j] = t;
    }

    float4 a[4], v[4];
#pragma unroll
    for (int j = 0; j < 4; j++) {
        a[j] = __ldg((const float4*)(g_xs_h + ((size_t)sIdx[j] << 7) + (sub << 3)));
        v[j] = __ldg((const float4*)(g_z_h  + ((size_t)tIdx[j] << 7) + (sub << 3)));
    }

    const float bv = __ldg(bias);

#pragma unroll
    for (int j = 0; j < 4; j++) {
        float acc = dot8h(a[j], v[j]);
#pragma unroll
        for (int o = 8; o > 0; o >>= 1)
            acc += __shfl_down_sync(0xFFFFFFFFu, acc, o, 16);
        if (sub == 0 && (e0 + 2 * j + half) < E)
            out[eidx[j]] = acc + bv;
    }
}

// ---------------------------------------------------------------------------
extern "C" void kernel_launch(void* const* d_in, const int* in_sizes, int n_in,
                              void* d_out, int out_size) {
    const float* x_source = nullptr;
    const float* x_target = nullptr;
    const void*  eli      = nullptr;
    const float* W        = nullptr;
    const float* bias     = nullptr;
    int N = 0;
    const int E = out_size;

    for (int i = 0; i < n_in; i++) {
        int sz = in_sizes[i];
        if (sz == NDIM * NDIM)      W    = (const float*)d_in[i];
        else if (sz == 1)           bias = (const float*)d_in[i];
        else if (sz == 2 * E)       eli  = d_in[i];
        else {
            if (!x_source) { x_source = (const float*)d_in[i]; N = sz / NDIM; }
            else           { x_target = (const float*)d_in[i]; }
        }
    }

    float* out = (float*)d_out;

    // 0) detect index dtype
    int nwords = 2 * E; if (nwords > 4096) nwords = 4096;
    detect_idx_kernel<<<1, 256>>>((const int*)eli, nwords);

    // 1) convert x_source -> fp16
    int n_elem4 = (N * NDIM) / 4;
    convert_xs_kernel<<<(n_elem4 + 255) / 256, 256>>>(x_source, n_elem4);

    // 2) z = x_target @ W^T via tensor cores (128 rows per block)
    gemm_mma_kernel<<<(N + 127) / 128, 256>>>(x_target, W, N);

    // 3) per-edge gather + dot
    int warps_needed = (E + EDGES_PER_WARP - 1) / EDGES_PER_WARP;
    int nblocks = (warps_needed + 7) / 8;
    edge_dot_kernel<<<nblocks, 256>>>(eli, bias, out, E, N);
}

// round 12
// speedup vs baseline: 1.7634x; 1.2023x over previous
#include <cuda_runtime.h>
#include <cuda_fp16.h>
#include <cstdint>

#define NDIM 128
#define MAX_NODES 100000

// Scratch: fp16 z table, fp16 x_source copy, dtype flag.
__device__ __half g_z_h[MAX_NODES * NDIM];    // 25.6 MB
__device__ __half g_xs_h[MAX_NODES * NDIM];   // 25.6 MB
__device__ int    g_idx_is64;

// ---------------------------------------------------------------------------
// Kernel 0: detect index dtype (int64 values < 2^31 -> all odd words zero).
// ---------------------------------------------------------------------------
__global__ void detect_idx_kernel(const int* __restrict__ idx_words, int nwords) {
    __shared__ int s_any_nonzero;
    if (threadIdx.x == 0) s_any_nonzero = 0;
    __syncthreads();
    for (int i = 1 + 2 * threadIdx.x; i < nwords; i += 2 * blockDim.x) {
        if (idx_words[i] != 0) { s_any_nonzero = 1; break; }
    }
    __syncthreads();
    if (threadIdx.x == 0) g_idx_is64 = (s_any_nonzero == 0) ? 1 : 0;
}

// ---------------------------------------------------------------------------
// Kernel 1: convert x_source -> fp16 (vectorized x4)
// ---------------------------------------------------------------------------
__global__ void __launch_bounds__(256) convert_xs_kernel(const float* __restrict__ xs,
                                                         int n_elem4) {
    int i = blockIdx.x * blockDim.x + threadIdx.x;
    if (i >= n_elem4) return;
    float4 v = *(const float4*)(xs + (size_t)i * 4);
    *(__half2*)(g_xs_h + (size_t)i * 4)     = __floats2half2_rn(v.x, v.y);
    *(__half2*)(g_xs_h + (size_t)i * 4 + 2) = __floats2half2_rn(v.z, v.w);
}

// ---------------------------------------------------------------------------
// Kernel 2: tensor-core GEMM  z[m][d] = sum_f xt[m][f] * W[d][f]
// mma.sync.m16n8k16.row.col.f32.f16.f16.f32
// 16 NAMED SCALAR accumulators (register arrays => lmem demotion => 128 MiB
// pool growth => harness violation; scalars proven safe R10/R11).
// K loop processes TWO k-steps per iteration to shorten the exposed
// LDG->MMA dependency chain (loop itself stays unroll 1).
// Block: 256 thr = 8 warps x 16 rows = 128 rows/block.
// ---------------------------------------------------------------------------
__global__ void __launch_bounds__(256) gemm_mma_kernel(const float* __restrict__ xt,
                                                       const float* __restrict__ W,
                                                       int n_rows) {
    __shared__ __half W_sh[NDIM][NDIM + 8];

    for (int i = threadIdx.x; i < NDIM * NDIM; i += 256) {
        int r = i >> 7;
        int c = i & (NDIM - 1);
        W_sh[r][c] = __float2half_rn(W[i]);
    }
    __syncthreads();

    const int warp = threadIdx.x >> 5;
    const int lane = threadIdx.x & 31;
    const int g = lane >> 2;        // 0..7
    const int t = lane & 3;         // 0..3
    const int row_base = blockIdx.x * 128 + warp * 16;
    if (row_base >= n_rows) return;

    // clamp fragment rows so tail blocks never read OOB (stores are guarded)
    int r0 = row_base + g;      if (r0 >= n_rows) r0 = n_rows - 1;
    int r1 = row_base + g + 8;  if (r1 >= n_rows) r1 = n_rows - 1;
    const float* A0 = xt + (size_t)r0 * NDIM + 2 * t;
    const float* A1 = xt + (size_t)r1 * NDIM + 2 * t;

    const int row0 = row_base + g;
    const int row1 = row_base + g + 8;

#define LOAD_A(k0, a0, a1, a2, a3)                                       \
    unsigned int a0, a1, a2, a3;                                          \
    {                                                                     \
        float2 f0 = *(const float2*)(A0 + (k0));                          \
        float2 f1 = *(const float2*)(A1 + (k0));                          \
        float2 f2 = *(const float2*)(A0 + (k0) + 8);                      \
        float2 f3 = *(const float2*)(A1 + (k0) + 8);                      \
        __half2 h0 = __floats2half2_rn(f0.x, f0.y);                       \
        __half2 h1 = __floats2half2_rn(f1.x, f1.y);                       \
        __half2 h2 = __floats2half2_rn(f2.x, f2.y);                       \
        __half2 h3 = __floats2half2_rn(f3.x, f3.y);                       \
        a0 = *(unsigned int*)&h0; a1 = *(unsigned int*)&h1;               \
        a2 = *(unsigned int*)&h2; a3 = *(unsigned int*)&h3;               \
    }

#define MMA_STEP(k0, A0r, A1r, A2r, A3r, C0, C1, C2, C3, NROW)                 \
    {                                                                          \
        unsigned int b0 = *(const unsigned int*)&W_sh[(NROW) + g][(k0) + 2 * t]; \
        unsigned int b1 = *(const unsigned int*)&W_sh[(NROW) + g][(k0) + 2 * t + 8]; \
        asm volatile(                                                          \
            "mma.sync.aligned.m16n8k16.row.col.f32.f16.f16.f32 "               \
            "{%0,%1,%2,%3}, {%4,%5,%6,%7}, {%8,%9}, {%0,%1,%2,%3};"            \
            : "+f"(C0), "+f"(C1), "+f"(C2), "+f"(C3)                           \
            : "r"(A0r), "r"(A1r), "r"(A2r), "r"(A3r), "r"(b0), "r"(b1));       \
    }

#pragma unroll 1
    for (int ntg = 0; ntg < 4; ntg++) {
        const int n0 = ntg * 32;
        float c00 = 0.f, c01 = 0.f, c02 = 0.f, c03 = 0.f;
        float c10 = 0.f, c11 = 0.f, c12 = 0.f, c13 = 0.f;
        float c20 = 0.f, c21 = 0.f, c22 = 0.f, c23 = 0.f;
        float c30 = 0.f, c31 = 0.f, c32 = 0.f, c33 = 0.f;

#pragma unroll 1
        for (int k0 = 0; k0 < NDIM; k0 += 32) {
            LOAD_A(k0,      p0, p1, p2, p3)
            LOAD_A(k0 + 16, q0, q1, q2, q3)

            MMA_STEP(k0, p0, p1, p2, p3, c00, c01, c02, c03, n0)
            MMA_STEP(k0, p0, p1, p2, p3, c10, c11, c12, c13, n0 + 8)
            MMA_STEP(k0, p0, p1, p2, p3, c20, c21, c22, c23, n0 + 16)
            MMA_STEP(k0, p0, p1, p2, p3, c30, c31, c32, c33, n0 + 24)

            MMA_STEP(k0 + 16, q0, q1, q2, q3, c00, c01, c02, c03, n0)
            MMA_STEP(k0 + 16, q0, q1, q2, q3, c10, c11, c12, c13, n0 + 8)
            MMA_STEP(k0 + 16, q0, q1, q2, q3, c20, c21, c22, c23, n0 + 16)
            MMA_STEP(k0 + 16, q0, q1, q2, q3, c30, c31, c32, c33, n0 + 24)
        }

        const int colb = n0 + 2 * t;
        if (row0 < n_rows) {
            __half* zp = g_z_h + (size_t)row0 * NDIM;
            *(__half2*)(zp + colb)      = __floats2half2_rn(c00, c01);
            *(__half2*)(zp + colb + 8)  = __floats2half2_rn(c10, c11);
            *(__half2*)(zp + colb + 16) = __floats2half2_rn(c20, c21);
            *(__half2*)(zp + colb + 24) = __floats2half2_rn(c30, c31);
        }
        if (row1 < n_rows) {
            __half* zp = g_z_h + (size_t)row1 * NDIM;
            *(__half2*)(zp + colb)      = __floats2half2_rn(c02, c03);
            *(__half2*)(zp + colb + 8)  = __floats2half2_rn(c12, c13);
            *(__half2*)(zp + colb + 16) = __floats2half2_rn(c22, c23);
            *(__half2*)(zp + colb + 24) = __floats2half2_rn(c32, c33);
        }
    }
#undef LOAD_A
#undef MMA_STEP
}

// ---------------------------------------------------------------------------
// Kernel 3: per-edge dot on fp16 tables.
// Instruction diet vs R11: HMUL2 products + fp32 sum (no fp16 accumulation,
// only per-product rounding), single unsigned min per index, tail via min.
// ---------------------------------------------------------------------------
__device__ __forceinline__ float dot8h(float4 a, float4 v) {
    const __half2* ah = (const __half2*)&a;
    const __half2* vh = (const __half2*)&v;
    __half2 p0 = __hmul2(ah[0], vh[0]);
    __half2 p1 = __hmul2(ah[1], vh[1]);
    __half2 p2 = __hmul2(ah[2], vh[2]);
    __half2 p3 = __hmul2(ah[3], vh[3]);
    float2 q0 = __half22float2(p0);
    float2 q1 = __half22float2(p1);
    float2 q2 = __half22float2(p2);
    float2 q3 = __half22float2(p3);
    return ((q0.x + q0.y) + (q1.x + q1.y)) + ((q2.x + q2.y) + (q3.x + q3.y));
}

#define EDGES_PER_WARP 8

__global__ void __launch_bounds__(256) edge_dot_kernel(
    const void* __restrict__ eli_raw,
    const float* __restrict__ bias,
    float* __restrict__ out,
    int E, unsigned int Nm1) {
    const int gwarp = (blockIdx.x * blockDim.x + threadIdx.x) >> 5;
    const int lane  = threadIdx.x & 31;
    const int half  = lane >> 4;
    const int sub   = lane & 15;

    const int e0 = gwarp * EDGES_PER_WARP;
    if (e0 >= E) return;

    const int is64 = g_idx_is64;
    const long long* eli64 = (const long long*)eli_raw;
    const int*       eli32 = (const int*)eli_raw;

    unsigned int sIdx[4], tIdx[4];
    int eidx[4];
#pragma unroll
    for (int j = 0; j < 4; j++) {
        int e = min(e0 + 2 * j + half, E - 1);   // tail-safe duplicate work
        eidx[j] = e;
        unsigned int s, t;
        if (is64) {
            s = (unsigned int)__ldg(&eli64[e]);
            t = (unsigned int)__ldg(&eli64[(long long)E + e]);
        } else {
            s = (unsigned int)__ldg(&eli32[e]);
            t = (unsigned int)__ldg(&eli32[(long long)E + e]);
        }
        sIdx[j] = min(s, Nm1);
        tIdx[j] = min(t, Nm1);
    }

    float4 a[4], v[4];
#pragma unroll
    for (int j = 0; j < 4; j++) {
        a[j] = __ldg((const float4*)(g_xs_h + ((size_t)sIdx[j] << 7) + (sub << 3)));
        v[j] = __ldg((const float4*)(g_z_h  + ((size_t)tIdx[j] << 7) + (sub << 3)));
    }

    const float bv = __ldg(bias);

#pragma unroll
    for (int j = 0; j < 4; j++) {
        float acc = dot8h(a[j], v[j]);
#pragma unroll
        for (int o = 8; o > 0; o >>= 1)
            acc += __shfl_down_sync(0xFFFFFFFFu, acc, o, 16);
        if (sub == 0)
            out[eidx[j]] = acc + bv;   // tail duplicates write identical values
    }
}

// ---------------------------------------------------------------------------
extern "C" void kernel_launch(void* const* d_in, const int* in_sizes, int n_in,
                              void* d_out, int out_size) {
    const float* x_source = nullptr;
    const float* x_target = nullptr;
    const void*  eli      = nullptr;
    const float* W        = nullptr;
    const float* bias     = nullptr;
    int N = 0;
    const int E = out_size;

    for (int i = 0; i < n_in; i++) {
        int sz = in_sizes[i];
        if (sz == NDIM * NDIM)      W    = (const float*)d_in[i];
        else if (sz == 1)           bias = (const float*)d_in[i];
        else if (sz == 2 * E)       eli  = d_in[i];
        else {
            if (!x_source) { x_source = (const float*)d_in[i]; N = sz / NDIM; }
            else           { x_target = (const float*)d_in[i]; }
        }
    }

    float* out = (float*)d_out;

    // 0) detect index dtype
    int nwords = 2 * E; if (nwords > 4096) nwords = 4096;
    detect_idx_kernel<<<1, 256>>>((const int*)eli, nwords);

    // 1) convert x_source -> fp16
    int n_elem4 = (N * NDIM) / 4;
    convert_xs_kernel<<<(n_elem4 + 255) / 256, 256>>>(x_source, n_elem4);

    // 2) z = x_target @ W^T via tensor cores (128 rows per block)
    gemm_mma_kernel<<<(N + 127) / 128, 256>>>(x_target, W, N);

    // 3) per-edge gather + dot
    int warps_needed = (E + EDGES_PER_WARP - 1) / EDGES_PER_WARP;
    int nblocks = (warps_needed + 7) / 8;
    edge_dot_kernel<<<nblocks, 256>>>(eli, bias, out, E, (unsigned int)(N - 1));
}